// round 6
// baseline (speedup 1.0000x reference)
#include <cuda_runtime.h>
#include <cuda_bf16.h>
#include <cfloat>

#define NN  50000
#define EE  1600000
#define FIN 8
#define HIDD 1000
#define RR  100

// ---------------- scratch (no allocations allowed) ----------------
__device__ int   g_cnt[NN];        // in-degree (count pass)
__device__ int   g_off[NN + 1];    // CSR offsets (exclusive scan of cnt)
__device__ int   g_cur[NN];        // scatter cursors (copy of offsets)
__device__ int   g_src[EE];        // CSR: source node per edge, grouped by dst
__device__ float g_x[NN];          // embedding (MLP input)
__device__ float g_h0[HIDD];
__device__ float g_h1[HIDD];
__device__ int   g_idx64;          // 1 if edge_index is int64, 0 if int32

// ---------------- helpers ----------------
__device__ __forceinline__ float dot8(float4 a, float4 b, const float* __restrict__ w) {
    return a.x * w[0] + a.y * w[1] + a.z * w[2] + a.w * w[3]
         + b.x * w[4] + b.y * w[5] + b.z * w[6] + b.w * w[7];
}

// ---------------- kernels ----------------

// Zero degree counters; thread 0 also sniffs the edge-index dtype.
// int32 data reinterpreted as int64 packs two random ids into one word ->
// out-of-range values with overwhelming probability over 16 samples.
__global__ void zero_detect_kernel(const long long* __restrict__ ei) {
    int i = blockIdx.x * blockDim.x + threadIdx.x;
    if (i < NN) g_cnt[i] = 0;
    if (i == 0) {
        int ok = 1;
        #pragma unroll
        for (int k = 0; k < 16; k++) {
            long long v = ei[k];
            if (v < 0 || v >= (long long)NN) ok = 0;
        }
        g_idx64 = ok;
    }
}

__global__ void count_kernel(const void* __restrict__ eiv) {
    int e = blockIdx.x * blockDim.x + threadIdx.x;
    if (e >= EE) return;
    int d = g_idx64 ? (int)((const long long*)eiv)[EE + e]
                    : ((const int*)eiv)[EE + e];
    atomicAdd(&g_cnt[d], 1);
}

// Single-block exclusive scan over g_cnt -> g_off / g_cur. 1024 threads,
// warp-shuffle scans, 2 barriers per 1024-chunk (49 chunks).
__global__ void scan_kernel() {
    __shared__ int warp_tot[32];
    __shared__ int s_base;
    int tid = threadIdx.x, lane = tid & 31, wid = tid >> 5;
    if (tid == 0) s_base = 0;
    __syncthreads();
    for (int chunk = 0; chunk < NN; chunk += 1024) {
        int idx = chunk + tid;
        int v = (idx < NN) ? g_cnt[idx] : 0;
        int x = v;
        #pragma unroll
        for (int o = 1; o < 32; o <<= 1) {
            int y = __shfl_up_sync(0xffffffffu, x, o);
            if (lane >= o) x += y;
        }
        if (lane == 31) warp_tot[wid] = x;
        __syncthreads();
        if (wid == 0) {
            int t = warp_tot[lane];
            #pragma unroll
            for (int o = 1; o < 32; o <<= 1) {
                int y = __shfl_up_sync(0xffffffffu, t, o);
                if (lane >= o) t += y;
            }
            warp_tot[lane] = t;  // inclusive per-warp totals
        }
        __syncthreads();
        int warp_excl = (wid == 0) ? 0 : warp_tot[wid - 1];
        int excl = s_base + warp_excl + x - v;
        if (idx < NN) { g_off[idx] = excl; g_cur[idx] = excl; }
        __syncthreads();
        if (tid == 0) s_base += warp_tot[31];
        __syncthreads();
    }
    if (threadIdx.x == 0) g_off[NN] = s_base;
}

__global__ void scatter_kernel(const void* __restrict__ eiv) {
    int e = blockIdx.x * blockDim.x + threadIdx.x;
    if (e >= EE) return;
    int s, d;
    if (g_idx64) {
        const long long* ei = (const long long*)eiv;
        s = (int)ei[e];
        d = (int)ei[EE + e];
    } else {
        const int* ei = (const int*)eiv;
        s = ei[e];
        d = ei[EE + e];
    }
    int pos = atomicAdd(&g_cur[d], 1);
    g_src[pos] = s;
}

// One warp per destination node: lanes stride its CSR edge range, accumulate
// per-feature max + mean-path dot locally, warp-shuffle reduce, lane 0 writes
// the fused SAGE embedding. Zero atomics.
__global__ void gather_kernel(const float* __restrict__ X,
                              const float* __restrict__ lin_l_w,
                              const float* __restrict__ lin_l_b,
                              const float* __restrict__ lin_r_w,
                              const float* __restrict__ lin_l1_w,
                              const float* __restrict__ lin_l1_b,
                              const float* __restrict__ lin_r1_w,
                              float* __restrict__ out) {
    int w = (blockIdx.x * blockDim.x + threadIdx.x) >> 5;
    int lane = threadIdx.x & 31;
    if (w >= NN) return;
    int start = g_off[w], end = g_off[w + 1];

    float m0 = -FLT_MAX, m1 = -FLT_MAX, m2 = -FLT_MAX, m3 = -FLT_MAX;
    float m4 = -FLT_MAX, m5 = -FLT_MAX, m6 = -FLT_MAX, m7 = -FLT_MAX;
    float sp = 0.0f;
    for (int i = start + lane; i < end; i += 32) {
        int s = g_src[i];
        const float4* x4 = (const float4*)(X + (size_t)s * FIN);
        float4 a = x4[0], b = x4[1];
        m0 = fmaxf(m0, a.x); m1 = fmaxf(m1, a.y);
        m2 = fmaxf(m2, a.z); m3 = fmaxf(m3, a.w);
        m4 = fmaxf(m4, b.x); m5 = fmaxf(m5, b.y);
        m6 = fmaxf(m6, b.z); m7 = fmaxf(m7, b.w);
        sp += dot8(a, b, lin_l_w);
    }
    #pragma unroll
    for (int o = 16; o; o >>= 1) {
        m0 = fmaxf(m0, __shfl_xor_sync(0xffffffffu, m0, o));
        m1 = fmaxf(m1, __shfl_xor_sync(0xffffffffu, m1, o));
        m2 = fmaxf(m2, __shfl_xor_sync(0xffffffffu, m2, o));
        m3 = fmaxf(m3, __shfl_xor_sync(0xffffffffu, m3, o));
        m4 = fmaxf(m4, __shfl_xor_sync(0xffffffffu, m4, o));
        m5 = fmaxf(m5, __shfl_xor_sync(0xffffffffu, m5, o));
        m6 = fmaxf(m6, __shfl_xor_sync(0xffffffffu, m6, o));
        m7 = fmaxf(m7, __shfl_xor_sync(0xffffffffu, m7, o));
        sp += __shfl_xor_sync(0xffffffffu, sp, o);
    }
    if (lane == 0) {
        int cnt = end - start;
        float mean = sp / fmaxf((float)cnt, 1.0f);   // agg_mean . lin_l_w
        float mx = 0.0f;
        if (cnt > 0) {
            mx = m0 * lin_l1_w[0] + m1 * lin_l1_w[1] + m2 * lin_l1_w[2] + m3 * lin_l1_w[3]
               + m4 * lin_l1_w[4] + m5 * lin_l1_w[5] + m6 * lin_l1_w[6] + m7 * lin_l1_w[7];
        }
        const float4* x4 = (const float4*)(X + (size_t)w * FIN);
        float4 a = x4[0], b = x4[1];
        float hm = fmaxf(mean + lin_l_b[0]  + dot8(a, b, lin_r_w),  0.0f);
        float hx = fmaxf(mx   + lin_l1_b[0] + dot8(a, b, lin_r1_w), 0.0f);
        float v = hm + hx;
        out[w] = v;   // X_embedding slot of output
        g_x[w] = v;   // MLP input
    }
}

// y[row] = relu(W[row,:] . x + b[row]); one block per row, float4 streaming.
__global__ void gemv_relu_kernel(const float* __restrict__ W,
                                 const float* __restrict__ b,
                                 const float* __restrict__ x,
                                 float* __restrict__ y,
                                 int in4) {  // in_dim / 4
    int row = blockIdx.x;
    const float4* w4 = (const float4*)(W + (size_t)row * (size_t)in4 * 4);
    const float4* x4 = (const float4*)x;
    float acc = 0.0f;
    #pragma unroll 4
    for (int c = threadIdx.x; c < in4; c += blockDim.x) {
        float4 w = w4[c];
        float4 v = x4[c];
        acc += w.x * v.x + w.y * v.y + w.z * v.z + w.w * v.w;
    }
    __shared__ float sh[32];
    #pragma unroll
    for (int o = 16; o; o >>= 1) acc += __shfl_down_sync(0xffffffffu, acc, o);
    int lane = threadIdx.x & 31, wid = threadIdx.x >> 5;
    if (lane == 0) sh[wid] = acc;
    __syncthreads();
    if (wid == 0) {
        int nw = blockDim.x >> 5;
        acc = (lane < nw) ? sh[lane] : 0.0f;
        #pragma unroll
        for (int o = 16; o; o >>= 1) acc += __shfl_down_sync(0xffffffffu, acc, o);
        if (lane == 0) y[row] = fmaxf(acc + b[row], 0.0f);
    }
}

// ---------------- launch ----------------
extern "C" void kernel_launch(void* const* d_in, const int* in_sizes, int n_in,
                              void* d_out, int out_size) {
    const float* X        = (const float*)d_in[0];
    const void*  ei       = d_in[1];               // int64 or int32, detected on device
    const float* lin_l_w  = (const float*)d_in[2];
    const float* lin_l_b  = (const float*)d_in[3];
    const float* lin_r_w  = (const float*)d_in[4];
    const float* lin_l1_w = (const float*)d_in[5];
    const float* lin_l1_b = (const float*)d_in[6];
    const float* lin_r1_w = (const float*)d_in[7];
    const float* W0       = (const float*)d_in[8];
    const float* b0       = (const float*)d_in[9];
    const float* W1       = (const float*)d_in[10];
    const float* b1       = (const float*)d_in[11];
    const float* W2       = (const float*)d_in[12];
    const float* b2       = (const float*)d_in[13];
    float* out = (float*)d_out;  // [NN + RR] = embedding ++ mlp_out

    zero_detect_kernel<<<(NN + 255) / 256, 256>>>((const long long*)ei);
    count_kernel<<<(EE + 255) / 256, 256>>>(ei);
    scan_kernel<<<1, 1024>>>();
    scatter_kernel<<<(EE + 255) / 256, 256>>>(ei);
    gather_kernel<<<(NN * 32 + 255) / 256, 256>>>(X, lin_l_w, lin_l_b, lin_r_w,
                                                  lin_l1_w, lin_l1_b, lin_r1_w, out);

    float* g_x_ptr;  float* g_h0_ptr;  float* g_h1_ptr;
    cudaGetSymbolAddress((void**)&g_x_ptr,  g_x);
    cudaGetSymbolAddress((void**)&g_h0_ptr, g_h0);
    cudaGetSymbolAddress((void**)&g_h1_ptr, g_h1);

    gemv_relu_kernel<<<HIDD, 256>>>(W0, b0, g_x_ptr,  g_h0_ptr, NN / 4);    // 1000 x 50000
    gemv_relu_kernel<<<HIDD, 256>>>(W1, b1, g_h0_ptr, g_h1_ptr, HIDD / 4);  // 1000 x 1000
    gemv_relu_kernel<<<RR,   256>>>(W2, b2, g_h1_ptr, out + NN, HIDD / 4);  // 100 x 1000
}

// round 8
// speedup vs baseline: 1.6066x; 1.6066x over previous
#include <cuda_runtime.h>
#include <cuda_bf16.h>
#include <cfloat>

#define NN  50000
#define EE  1600000
#define FIN 8
#define HIDD 1000
#define RR  100
#define PACK24 16777216.0   // 2^24: g_sc = sum + cnt * 2^24 (exact unpack)

// ---------------- scratch (no allocations allowed) ----------------
__device__ double               g_sc[NN];            // packed (sum of p, count)
__device__ __align__(16) unsigned g_maxk[NN * FIN];  // encoded per-feature running max
__device__ __align__(16) unsigned g_key[NN * FIN];   // encoded X features per node
__device__ float g_p[NN];         // dot(X[i], lin_l_w) per node (mean path)
__device__ float g_x[NN];         // embedding (MLP input)
__device__ float g_h0[HIDD];
__device__ float g_h1[HIDD];
__device__ int   g_idx64;         // 1 if edge_index is int64, 0 if int32

// ---------------- helpers ----------------
// Order-preserving float -> uint32 encoding (monotone; larger float => larger key).
__device__ __forceinline__ unsigned encf(float f) {
    unsigned u = __float_as_uint(f);
    return (u & 0x80000000u) ? ~u : (u | 0x80000000u);
}
__device__ __forceinline__ float decf(unsigned k) {
    return (k & 0x80000000u) ? __uint_as_float(k & 0x7fffffffu)
                             : __uint_as_float(~k);
}
__device__ __forceinline__ float dot8(float4 a, float4 b, const float* __restrict__ w) {
    return a.x * w[0] + a.y * w[1] + a.z * w[2] + a.w * w[3]
         + b.x * w[4] + b.y * w[5] + b.z * w[6] + b.w * w[7];
}

// ---------------- kernels ----------------

// Per node: zero accumulators, precompute p[i] and encoded keys from X.
// Thread 0 sniffs edge-index dtype: int32 data reinterpreted as int64 packs two
// random ids per word -> out-of-range values w.p. ~1 over 16 samples.
__global__ void init_kernel(const float* __restrict__ X,
                            const float* __restrict__ lin_l_w,
                            const long long* __restrict__ ei) {
    int i = blockIdx.x * blockDim.x + threadIdx.x;
    if (i == 0) {
        int ok = 1;
        #pragma unroll
        for (int k = 0; k < 16; k++) {
            long long v = ei[k];
            if (v < 0 || v >= (long long)NN) ok = 0;
        }
        g_idx64 = ok;
    }
    if (i >= NN) return;
    g_sc[i] = 0.0;
    // init max keys to 0: every real key is > 0 (no -NaN inputs), masked by cnt anyway
    uint4 z = make_uint4(0u, 0u, 0u, 0u);
    ((uint4*)&g_maxk[(size_t)i * FIN])[0] = z;
    ((uint4*)&g_maxk[(size_t)i * FIN])[1] = z;
    const float4* x4 = (const float4*)(X + (size_t)i * FIN);
    float4 a = x4[0], b = x4[1];
    g_p[i] = dot8(a, b, lin_l_w);
    uint4 k0 = make_uint4(encf(a.x), encf(a.y), encf(a.z), encf(a.w));
    uint4 k1 = make_uint4(encf(b.x), encf(b.y), encf(b.z), encf(b.w));
    ((uint4*)&g_key[(size_t)i * FIN])[0] = k0;
    ((uint4*)&g_key[(size_t)i * FIN])[1] = k1;
}

__device__ __forceinline__ void process_edge(int s, int d) {
    // mean path + count: single 64-bit RED
    atomicAdd(&g_sc[d], (double)__ldg(&g_p[s]) + PACK24);
    // max path: read-filtered atomicMax (monotone => stale reads are safe)
    uint4 k0 = ((const uint4*)&g_key[(size_t)s * FIN])[0];
    uint4 k1 = ((const uint4*)&g_key[(size_t)s * FIN])[1];
    unsigned* m = &g_maxk[(size_t)d * FIN];
    uint4 c0 = ((const uint4*)m)[0];
    uint4 c1 = ((const uint4*)m)[1];
    if (k0.x > c0.x) atomicMax(m + 0, k0.x);
    if (k0.y > c0.y) atomicMax(m + 1, k0.y);
    if (k0.z > c0.z) atomicMax(m + 2, k0.z);
    if (k0.w > c0.w) atomicMax(m + 3, k0.w);
    if (k1.x > c1.x) atomicMax(m + 4, k1.x);
    if (k1.y > c1.y) atomicMax(m + 5, k1.y);
    if (k1.z > c1.z) atomicMax(m + 6, k1.z);
    if (k1.w > c1.w) atomicMax(m + 7, k1.w);
}

// Two edges per thread, vectorized index loads (EE even; offsets 16B-aligned).
__global__ void edge_kernel(const void* __restrict__ eiv) {
    int t = blockIdx.x * blockDim.x + threadIdx.x;
    if (t * 2 >= EE) return;
    int s0, d0, s1, d1;
    if (g_idx64) {
        const longlong2* S = (const longlong2*)eiv;
        const longlong2* D = (const longlong2*)((const long long*)eiv + EE);
        longlong2 sv = S[t], dv = D[t];
        s0 = (int)sv.x; s1 = (int)sv.y;
        d0 = (int)dv.x; d1 = (int)dv.y;
    } else {
        const int2* S = (const int2*)eiv;
        const int2* D = (const int2*)((const int*)eiv + EE);
        int2 sv = S[t], dv = D[t];
        s0 = sv.x; s1 = sv.y;
        d0 = dv.x; d1 = dv.y;
    }
    process_edge(s0, d0);
    process_edge(s1, d1);
}

__global__ void node_kernel(const float* __restrict__ X,
                            const float* __restrict__ lin_l_b,
                            const float* __restrict__ lin_r_w,
                            const float* __restrict__ lin_l1_w,
                            const float* __restrict__ lin_l1_b,
                            const float* __restrict__ lin_r1_w,
                            float* __restrict__ out) {
    int i = blockIdx.x * blockDim.x + threadIdx.x;
    if (i >= NN) return;
    double acc = g_sc[i];
    int cnt = __double2int_rn(acc * (1.0 / PACK24));
    float sum = (float)(acc - (double)cnt * PACK24);
    float mean = sum / fmaxf((float)cnt, 1.0f);       // agg_mean . lin_l_w
    float mx = 0.0f;
    if (cnt > 0) {
        const uint4* mk = (const uint4*)&g_maxk[(size_t)i * FIN];
        uint4 c0 = mk[0], c1 = mk[1];
        mx = decf(c0.x) * lin_l1_w[0] + decf(c0.y) * lin_l1_w[1]
           + decf(c0.z) * lin_l1_w[2] + decf(c0.w) * lin_l1_w[3]
           + decf(c1.x) * lin_l1_w[4] + decf(c1.y) * lin_l1_w[5]
           + decf(c1.z) * lin_l1_w[6] + decf(c1.w) * lin_l1_w[7];
    }
    const float4* x4 = (const float4*)(X + (size_t)i * FIN);
    float4 a = x4[0], b = x4[1];
    float hm = fmaxf(mean + lin_l_b[0]  + dot8(a, b, lin_r_w),  0.0f);
    float hx = fmaxf(mx   + lin_l1_b[0] + dot8(a, b, lin_r1_w), 0.0f);
    float v = hm + hx;
    out[i] = v;   // X_embedding slot of output
    g_x[i] = v;   // MLP input
}

// y[row] = relu(W[row,:] . x + b[row]); one block per row, float4 streaming.
template <int THREADS>
__global__ void gemv_relu_kernel(const float* __restrict__ W,
                                 const float* __restrict__ b,
                                 const float* __restrict__ x,
                                 float* __restrict__ y,
                                 int in4) {  // in_dim / 4
    int row = blockIdx.x;
    const float4* w4 = (const float4*)(W + (size_t)row * (size_t)in4 * 4);
    const float4* x4 = (const float4*)x;
    float acc = 0.0f;
    int c = threadIdx.x;
    // main unrolled stream (deep MLP for the 200MB W0 read)
    for (; c + 3 * THREADS < in4; c += 4 * THREADS) {
        float4 w0 = w4[c];
        float4 w1 = w4[c + THREADS];
        float4 w2 = w4[c + 2 * THREADS];
        float4 w3 = w4[c + 3 * THREADS];
        float4 v0 = x4[c];
        float4 v1 = x4[c + THREADS];
        float4 v2 = x4[c + 2 * THREADS];
        float4 v3 = x4[c + 3 * THREADS];
        acc += w0.x * v0.x + w0.y * v0.y + w0.z * v0.z + w0.w * v0.w;
        acc += w1.x * v1.x + w1.y * v1.y + w1.z * v1.z + w1.w * v1.w;
        acc += w2.x * v2.x + w2.y * v2.y + w2.z * v2.z + w2.w * v2.w;
        acc += w3.x * v3.x + w3.y * v3.y + w3.z * v3.z + w3.w * v3.w;
    }
    for (; c < in4; c += THREADS) {
        float4 w = w4[c];
        float4 v = x4[c];
        acc += w.x * v.x + w.y * v.y + w.z * v.z + w.w * v.w;
    }
    __shared__ float sh[THREADS / 32];
    #pragma unroll
    for (int o = 16; o; o >>= 1) acc += __shfl_down_sync(0xffffffffu, acc, o);
    int lane = threadIdx.x & 31, wid = threadIdx.x >> 5;
    if (lane == 0) sh[wid] = acc;
    __syncthreads();
    if (wid == 0) {
        acc = (lane < THREADS / 32) ? sh[lane] : 0.0f;
        #pragma unroll
        for (int o = 16; o; o >>= 1) acc += __shfl_down_sync(0xffffffffu, acc, o);
        if (lane == 0) y[row] = fmaxf(acc + b[row], 0.0f);
    }
}

// ---------------- launch ----------------
extern "C" void kernel_launch(void* const* d_in, const int* in_sizes, int n_in,
                              void* d_out, int out_size) {
    const float* X        = (const float*)d_in[0];
    const void*  ei       = d_in[1];               // int64 or int32, detected on device
    const float* lin_l_w  = (const float*)d_in[2];
    const float* lin_l_b  = (const float*)d_in[3];
    const float* lin_r_w  = (const float*)d_in[4];
    const float* lin_l1_w = (const float*)d_in[5];
    const float* lin_l1_b = (const float*)d_in[6];
    const float* lin_r1_w = (const float*)d_in[7];
    const float* W0       = (const float*)d_in[8];
    const float* b0       = (const float*)d_in[9];
    const float* W1       = (const float*)d_in[10];
    const float* b1       = (const float*)d_in[11];
    const float* W2       = (const float*)d_in[12];
    const float* b2       = (const float*)d_in[13];
    float* out = (float*)d_out;  // [NN + RR] = embedding ++ mlp_out

    init_kernel<<<(NN + 255) / 256, 256>>>(X, lin_l_w, (const long long*)ei);
    edge_kernel<<<(EE / 2 + 255) / 256, 256>>>(ei);
    node_kernel<<<(NN + 255) / 256, 256>>>(X, lin_l_b, lin_r_w,
                                           lin_l1_w, lin_l1_b, lin_r1_w, out);

    float* g_x_ptr;  float* g_h0_ptr;  float* g_h1_ptr;
    cudaGetSymbolAddress((void**)&g_x_ptr,  g_x);
    cudaGetSymbolAddress((void**)&g_h0_ptr, g_h0);
    cudaGetSymbolAddress((void**)&g_h1_ptr, g_h1);

    gemv_relu_kernel<512><<<HIDD, 512>>>(W0, b0, g_x_ptr,  g_h0_ptr, NN / 4);    // 1000x50000
    gemv_relu_kernel<256><<<HIDD, 256>>>(W1, b1, g_h0_ptr, g_h1_ptr, HIDD / 4);  // 1000x1000
    gemv_relu_kernel<256><<<RR,   256>>>(W2, b2, g_h1_ptr, out + NN, HIDD / 4);  // 100x1000
}

// round 9
// speedup vs baseline: 2.2594x; 1.4064x over previous
#include <cuda_runtime.h>
#include <cuda_bf16.h>
#include <cfloat>

#define NN  50000
#define EE  1600000
#define FIN 8
#define HIDD 1000
#define RR  100
#define PACK24 16777216.0   // 2^24: g_sc = sum + cnt * 2^24 (exact unpack)

#define CH   10             // column chunks per GEMV0 row
#define C4   1250           // float4s per chunk (NN/4/CH)
#define R4   4              // rows per GEMV0 block

// ---------------- scratch (no allocations allowed) ----------------
__device__ double                 g_sc[NN];          // packed (sum of p, count)
__device__ __align__(16) unsigned g_maxk[NN * FIN];  // encoded per-feature running max
__device__ __align__(16) unsigned g_key[NN * FIN];   // encoded X features per node
__device__ float g_x[NN];         // embedding (MLP input)
__device__ float g_h0pre[HIDD];   // GEMV0 pre-activation accumulator (seeded with b0)
__device__ float g_h1[HIDD];
__device__ int   g_idx64;         // 1 if edge_index is int64, 0 if int32

// ---------------- helpers ----------------
// Order-preserving float <-> uint32 encoding (monotone, exact round-trip).
__device__ __forceinline__ unsigned encf(float f) {
    unsigned u = __float_as_uint(f);
    return (u & 0x80000000u) ? ~u : (u | 0x80000000u);
}
__device__ __forceinline__ float decf(unsigned k) {
    unsigned u = (k & 0x80000000u) ? (k & 0x7fffffffu) : ~k;
    return __uint_as_float(u);
}
__device__ __forceinline__ float dot8(float4 a, float4 b, const float* __restrict__ w) {
    return a.x * w[0] + a.y * w[1] + a.z * w[2] + a.w * w[3]
         + b.x * w[4] + b.y * w[5] + b.z * w[6] + b.w * w[7];
}
__device__ __forceinline__ float dot44(float4 a, float4 wa, float4 b, float4 wb) {
    return a.x * wa.x + a.y * wa.y + a.z * wa.z + a.w * wa.w
         + b.x * wb.x + b.y * wb.y + b.z * wb.z + b.w * wb.w;
}

// ---------------- kernels ----------------

// Per node: zero accumulators, encode keys from X; seed h0pre with b0.
// Thread 0 sniffs edge-index dtype: int32 data reinterpreted as int64 packs two
// random ids per word -> out-of-range values w.p. ~1 over 16 samples.
__global__ void init_kernel(const float* __restrict__ X,
                            const float* __restrict__ b0,
                            const long long* __restrict__ ei) {
    int i = blockIdx.x * blockDim.x + threadIdx.x;
    if (i == 0) {
        int ok = 1;
        #pragma unroll
        for (int k = 0; k < 16; k++) {
            long long v = ei[k];
            if (v < 0 || v >= (long long)NN) ok = 0;
        }
        g_idx64 = ok;
    }
    if (i < HIDD) g_h0pre[i] = b0[i];
    if (i >= NN) return;
    g_sc[i] = 0.0;
    // init max keys to 0: every real-data key is > 0; masked by cnt anyway
    uint4 z = make_uint4(0u, 0u, 0u, 0u);
    ((uint4*)&g_maxk[(size_t)i * FIN])[0] = z;
    ((uint4*)&g_maxk[(size_t)i * FIN])[1] = z;
    const float4* x4 = (const float4*)(X + (size_t)i * FIN);
    float4 a = x4[0], b = x4[1];
    uint4 k0 = make_uint4(encf(a.x), encf(a.y), encf(a.z), encf(a.w));
    uint4 k1 = make_uint4(encf(b.x), encf(b.y), encf(b.z), encf(b.w));
    ((uint4*)&g_key[(size_t)i * FIN])[0] = k0;
    ((uint4*)&g_key[(size_t)i * FIN])[1] = k1;
}

__device__ __forceinline__ void process_edge(int s, int d, float4 wa, float4 wb) {
    const uint4* kp = (const uint4*)&g_key[(size_t)s * FIN];
    uint4 k0 = __ldg(kp);
    uint4 k1 = __ldg(kp + 1);
    // p = dot(X[s], lin_l_w), decoded exactly from the keys (no extra array read)
    float4 xa = make_float4(decf(k0.x), decf(k0.y), decf(k0.z), decf(k0.w));
    float4 xb = make_float4(decf(k1.x), decf(k1.y), decf(k1.z), decf(k1.w));
    float p = dot44(xa, wa, xb, wb);
    // mean path + count in a single 64-bit RED
    atomicAdd(&g_sc[d], (double)p + PACK24);
    // max path: read-filtered atomicMax (monotone => stale reads are safe)
    unsigned* m = &g_maxk[(size_t)d * FIN];
    uint4 c0 = ((const uint4*)m)[0];
    uint4 c1 = ((const uint4*)m)[1];
    if (k0.x > c0.x) atomicMax(m + 0, k0.x);
    if (k0.y > c0.y) atomicMax(m + 1, k0.y);
    if (k0.z > c0.z) atomicMax(m + 2, k0.z);
    if (k0.w > c0.w) atomicMax(m + 3, k0.w);
    if (k1.x > c1.x) atomicMax(m + 4, k1.x);
    if (k1.y > c1.y) atomicMax(m + 5, k1.y);
    if (k1.z > c1.z) atomicMax(m + 6, k1.z);
    if (k1.w > c1.w) atomicMax(m + 7, k1.w);
}

// Four edges per thread, vectorized index loads (EE % 4 == 0).
__global__ void edge_kernel(const void* __restrict__ eiv,
                            const float* __restrict__ lin_l_w) {
    int t = blockIdx.x * blockDim.x + threadIdx.x;
    if (t * 4 >= EE) return;
    int s[4], d[4];
    if (g_idx64) {
        const longlong2* S = (const longlong2*)eiv;
        const longlong2* D = (const longlong2*)((const long long*)eiv + EE);
        longlong2 a = S[2 * t], b = S[2 * t + 1];
        longlong2 c = D[2 * t], e = D[2 * t + 1];
        s[0] = (int)a.x; s[1] = (int)a.y; s[2] = (int)b.x; s[3] = (int)b.y;
        d[0] = (int)c.x; d[1] = (int)c.y; d[2] = (int)e.x; d[3] = (int)e.y;
    } else {
        const int4* S = (const int4*)eiv;
        const int4* D = (const int4*)((const int*)eiv + EE);
        int4 a = S[t], c = D[t];
        s[0] = a.x; s[1] = a.y; s[2] = a.z; s[3] = a.w;
        d[0] = c.x; d[1] = c.y; d[2] = c.z; d[3] = c.w;
    }
    float4 wa = __ldg((const float4*)lin_l_w);
    float4 wb = __ldg((const float4*)lin_l_w + 1);
    #pragma unroll
    for (int k = 0; k < 4; k++) process_edge(s[k], d[k], wa, wb);
}

__global__ void node_kernel(const float* __restrict__ X,
                            const float* __restrict__ lin_l_b,
                            const float* __restrict__ lin_r_w,
                            const float* __restrict__ lin_l1_w,
                            const float* __restrict__ lin_l1_b,
                            const float* __restrict__ lin_r1_w,
                            float* __restrict__ out) {
    int i = blockIdx.x * blockDim.x + threadIdx.x;
    if (i >= NN) return;
    double acc = g_sc[i];
    int cnt = __double2int_rn(acc * (1.0 / PACK24));
    float sum = (float)(acc - (double)cnt * PACK24);
    float mean = sum / fmaxf((float)cnt, 1.0f);       // agg_mean . lin_l_w
    float mx = 0.0f;
    if (cnt > 0) {
        const uint4* mk = (const uint4*)&g_maxk[(size_t)i * FIN];
        uint4 c0 = mk[0], c1 = mk[1];
        mx = decf(c0.x) * lin_l1_w[0] + decf(c0.y) * lin_l1_w[1]
           + decf(c0.z) * lin_l1_w[2] + decf(c0.w) * lin_l1_w[3]
           + decf(c1.x) * lin_l1_w[4] + decf(c1.y) * lin_l1_w[5]
           + decf(c1.z) * lin_l1_w[6] + decf(c1.w) * lin_l1_w[7];
    }
    const float4* x4 = (const float4*)(X + (size_t)i * FIN);
    float4 a = x4[0], b = x4[1];
    float hm = fmaxf(mean + lin_l_b[0]  + dot8(a, b, lin_r_w),  0.0f);
    float hx = fmaxf(mx   + lin_l1_b[0] + dot8(a, b, lin_r1_w), 0.0f);
    float v = hm + hx;
    out[i] = v;   // X_embedding slot of output
    g_x[i] = v;   // MLP input
}

// GEMV0 split: block = (4 rows, 1 of 10 column chunks). x slice is loaded once
// and reused for 4 W rows (4x less L2 x-traffic); partials combined by atomicAdd
// into g_h0pre (pre-seeded with b0). Fine-grained units kill the wave tail.
__global__ void gemv0_partial_kernel(const float* __restrict__ W0,
                                     const float* __restrict__ x) {
    int rb    = blockIdx.x / CH;   // row group
    int chunk = blockIdx.x % CH;
    int row = rb * R4;
    const float4* x4 = (const float4*)x;
    const float4* w0 = (const float4*)(W0 + (size_t)(row + 0) * NN);
    const float4* w1 = (const float4*)(W0 + (size_t)(row + 1) * NN);
    const float4* w2 = (const float4*)(W0 + (size_t)(row + 2) * NN);
    const float4* w3 = (const float4*)(W0 + (size_t)(row + 3) * NN);
    float a0 = 0.f, a1 = 0.f, a2 = 0.f, a3 = 0.f;
    int base = chunk * C4;
    for (int c = base + threadIdx.x; c < base + C4; c += 256) {
        float4 v  = x4[c];
        float4 p0 = w0[c];
        float4 p1 = w1[c];
        float4 p2 = w2[c];
        float4 p3 = w3[c];
        a0 += p0.x * v.x + p0.y * v.y + p0.z * v.z + p0.w * v.w;
        a1 += p1.x * v.x + p1.y * v.y + p1.z * v.z + p1.w * v.w;
        a2 += p2.x * v.x + p2.y * v.y + p2.z * v.z + p2.w * v.w;
        a3 += p3.x * v.x + p3.y * v.y + p3.z * v.z + p3.w * v.w;
    }
    __shared__ float sh[8][4];
    #pragma unroll
    for (int o = 16; o; o >>= 1) {
        a0 += __shfl_down_sync(0xffffffffu, a0, o);
        a1 += __shfl_down_sync(0xffffffffu, a1, o);
        a2 += __shfl_down_sync(0xffffffffu, a2, o);
        a3 += __shfl_down_sync(0xffffffffu, a3, o);
    }
    int lane = threadIdx.x & 31, wid = threadIdx.x >> 5;
    if (lane == 0) { sh[wid][0] = a0; sh[wid][1] = a1; sh[wid][2] = a2; sh[wid][3] = a3; }
    __syncthreads();
    if (wid == 0 && lane < 4) {
        float s = sh[0][lane] + sh[1][lane] + sh[2][lane] + sh[3][lane]
                + sh[4][lane] + sh[5][lane] + sh[6][lane] + sh[7][lane];
        atomicAdd(&g_h0pre[row + lane], s);
    }
}

// y[row] = relu(W[row,:] . act(x) + b[row]); act = relu if RELU_IN (fused from GEMV0).
template <int THREADS, int RELU_IN>
__global__ void gemv_relu_kernel(const float* __restrict__ W,
                                 const float* __restrict__ b,
                                 const float* __restrict__ x,
                                 float* __restrict__ y,
                                 int in4) {  // in_dim / 4
    int row = blockIdx.x;
    const float4* w4 = (const float4*)(W + (size_t)row * (size_t)in4 * 4);
    const float4* x4 = (const float4*)x;
    float acc = 0.0f;
    for (int c = threadIdx.x; c < in4; c += THREADS) {
        float4 w = w4[c];
        float4 v = x4[c];
        if (RELU_IN) {
            v.x = fmaxf(v.x, 0.f); v.y = fmaxf(v.y, 0.f);
            v.z = fmaxf(v.z, 0.f); v.w = fmaxf(v.w, 0.f);
        }
        acc += w.x * v.x + w.y * v.y + w.z * v.z + w.w * v.w;
    }
    __shared__ float sh[THREADS / 32];
    #pragma unroll
    for (int o = 16; o; o >>= 1) acc += __shfl_down_sync(0xffffffffu, acc, o);
    int lane = threadIdx.x & 31, wid = threadIdx.x >> 5;
    if (lane == 0) sh[wid] = acc;
    __syncthreads();
    if (wid == 0) {
        acc = (lane < THREADS / 32) ? sh[lane] : 0.0f;
        #pragma unroll
        for (int o = 16; o; o >>= 1) acc += __shfl_down_sync(0xffffffffu, acc, o);
        if (lane == 0) y[row] = fmaxf(acc + b[row], 0.0f);
    }
}

// ---------------- launch ----------------
extern "C" void kernel_launch(void* const* d_in, const int* in_sizes, int n_in,
                              void* d_out, int out_size) {
    const float* X        = (const float*)d_in[0];
    const void*  ei       = d_in[1];               // int64 or int32, detected on device
    const float* lin_l_w  = (const float*)d_in[2];
    const float* lin_l_b  = (const float*)d_in[3];
    const float* lin_r_w  = (const float*)d_in[4];
    const float* lin_l1_w = (const float*)d_in[5];
    const float* lin_l1_b = (const float*)d_in[6];
    const float* lin_r1_w = (const float*)d_in[7];
    const float* W0       = (const float*)d_in[8];
    const float* b0       = (const float*)d_in[9];
    const float* W1       = (const float*)d_in[10];
    const float* b1       = (const float*)d_in[11];
    const float* W2       = (const float*)d_in[12];
    const float* b2       = (const float*)d_in[13];
    float* out = (float*)d_out;  // [NN + RR] = embedding ++ mlp_out

    init_kernel<<<(NN + 255) / 256, 256>>>(X, b0, (const long long*)ei);
    edge_kernel<<<(EE / 4 + 255) / 256, 256>>>(ei, lin_l_w);
    node_kernel<<<(NN + 255) / 256, 256>>>(X, lin_l_b, lin_r_w,
                                           lin_l1_w, lin_l1_b, lin_r1_w, out);

    float* g_x_ptr;  float* g_h0pre_ptr;  float* g_h1_ptr;
    cudaGetSymbolAddress((void**)&g_x_ptr,     g_x);
    cudaGetSymbolAddress((void**)&g_h0pre_ptr, g_h0pre);
    cudaGetSymbolAddress((void**)&g_h1_ptr,    g_h1);

    gemv0_partial_kernel<<<(HIDD / R4) * CH, 256>>>(W0, g_x_ptr);              // 1000x50000
    gemv_relu_kernel<256, 1><<<HIDD, 256>>>(W1, b1, g_h0pre_ptr, g_h1_ptr, HIDD / 4);
    gemv_relu_kernel<256, 0><<<RR,   256>>>(W2, b2, g_h1_ptr, out + NN, HIDD / 4);
}